// round 8
// baseline (speedup 1.0000x reference)
#include <cuda_runtime.h>
#include <math.h>

#define B1n 4
#define B2n 1024
#define Rn  64
#define Tn  8192
#define Ln  256

#define NBATCH   8      // receivers per batch (= warps per block)
#define NBATCHES 8      // Rn / NBATCH
#define WROW     260    // staged window floats per receiver (need 0..256)

// Per block (b1,b2): stage receiver windows into smem DESKEWED (shifted by -d),
// so compute needs no alignment select at all. Double-buffered batches of 8
// receivers; warp w stages receiver nb*8+w (65 contiguous LDG.128 -> ~9 L1
// wavefronts per r). Compute: 64 l-threads x 4 r-groups, each thread does one
// LDS.128 + one LDS.32 + 4 lerps per (r, 4 l's).

__global__ void __launch_bounds__(Ln)
tof_predictor_kernel(const float* __restrict__ rec,        // (B1,R,T)
                     const float* __restrict__ samp,       // (B1,B2,3)
                     const float* __restrict__ emit,       // (3,)
                     const float* __restrict__ recv,       // (R,3)
                     float* __restrict__ out)              // (B1,B2)
{
    const int b2  = blockIdx.x;
    const int b1  = blockIdx.y;
    const int tid = threadIdx.x;

    __shared__ float  s_win[2][NBATCH][WROW];   // deskewed windows (double buffer)
    __shared__ float2 s_pr[Rn];                 // {frac, as_float(((r*Tn+i0a)<<2)|d)}
    __shared__ float  s_s1[4 * Ln];
    __shared__ float  s_s2[4 * Ln];
    __shared__ float  s_red[16];

    // ---- precompute per-receiver aligned base + d + frac (threads 0..63) ----
    const float fs_c = 96000.0f / 343.0f;
    if (tid < Rn) {
        const float* sp = samp + ((size_t)b1 * B2n + b2) * 3;
        float sx = sp[0], sy = sp[1], sz = sp[2];
        float ex = sx - emit[0], ey = sy - emit[1], ez = sz - emit[2];
        float d_e = sqrtf(ex * ex + ey * ey + ez * ez);
        const float* rp = recv + tid * 3;
        float rx = sx - rp[0], ry = sy - rp[1], rz = sz - rp[2];
        float d_r = sqrtf(rx * rx + ry * ry + rz * rz);
        float start = (d_e + d_r) * fs_c;
        int i0 = (int)floorf(start);
        i0 = min(max(i0, 0), Tn - WROW - 8);        // never fires for this geometry
        float frac = start - (float)i0;             // in [0,1)
        int i0a = i0 & ~3;
        int d   = i0 & 3;
        int packed = ((tid * Tn + i0a) << 2) | d;   // float-index<<2 | d
        s_pr[tid] = make_float2(frac, __int_as_float(packed));
    }
    __syncthreads();

    const int warp = tid >> 5;
    const int lane = tid & 31;
    const int g = tid >> 6;        // r-group 0..3
    const int t = tid & 63;        // l-thread: l = 4t..4t+3

    const float4* rec4 = (const float4*)(rec + (size_t)b1 * Rn * Tn);

    float a0 = 0.f, a1 = 0.f, a2 = 0.f, a3 = 0.f;
    float q0 = 0.f, q1 = 0.f, q2 = 0.f, q3 = 0.f;

    // ---- stage batch 0 ----
    {
        float2 pr = s_pr[warp];
        int o = __float_as_int(pr.y);
        int d = o & 3;
        const float4* src = rec4 + (o >> 4);        // (r*Tn+i0a)/4
        float4 x0 = __ldg(src + lane);
        float4 x1 = __ldg(src + lane + 32);
        float4 x2 = (lane == 0) ? __ldg(src + 64) : make_float4(0, 0, 0, 0);
        float* dst = &s_win[0][warp][0];
        int k0 = 4 * lane - d;
        if (k0 >= 0) dst[k0] = x0.x;                // only lane 0, e<d skipped
        if (k0 + 1 >= 0) dst[k0 + 1] = x0.y;
        if (k0 + 2 >= 0) dst[k0 + 2] = x0.z;
        dst[k0 + 3] = x0.w;                          // 4*lane+3-d >= 0 always
        int k1 = 4 * (lane + 32) - d;
        dst[k1] = x1.x; dst[k1 + 1] = x1.y; dst[k1 + 2] = x1.z; dst[k1 + 3] = x1.w;
        if (lane == 0) {
            int k2 = 256 - d;
            dst[k2] = x2.x; dst[k2 + 1] = x2.y; dst[k2 + 2] = x2.z; dst[k2 + 3] = x2.w;
        }
    }
    __syncthreads();

#pragma unroll
    for (int nb = 0; nb < NBATCHES; ++nb) {
        const int buf = nb & 1;

        // ---- prefetch next batch's data into registers (no stores yet) ----
        float4 x0, x1, x2;
        int dn = 0;
        if (nb < NBATCHES - 1) {
            float2 pr = s_pr[(nb + 1) * NBATCH + warp];
            int o = __float_as_int(pr.y);
            dn = o & 3;
            const float4* src = rec4 + (o >> 4);
            x0 = __ldg(src + lane);
            x1 = __ldg(src + lane + 32);
            x2 = (lane == 0) ? __ldg(src + 64) : make_float4(0, 0, 0, 0);
        }

        // ---- compute on current batch: group g handles rloc = 2g, 2g+1 ----
#pragma unroll
        for (int h = 0; h < 2; ++h) {
            int rloc = 2 * g + h;
            float f = s_pr[nb * NBATCH + rloc].x;
            const float* row = &s_win[buf][rloc][0];
            float4 V = *(const float4*)(row + 4 * t);
            float v4 = row[4 * t + 4];

            float e0 = fmaf(f, V.y - V.x, V.x);
            float e1 = fmaf(f, V.z - V.y, V.y);
            float e2 = fmaf(f, V.w - V.z, V.z);
            float e3 = fmaf(f, v4 - V.w, V.w);

            a0 += e0; q0 = fmaf(e0, e0, q0);
            a1 += e1; q1 = fmaf(e1, e1, q1);
            a2 += e2; q2 = fmaf(e2, e2, q2);
            a3 += e3; q3 = fmaf(e3, e3, q3);
        }

        // ---- store next batch's data (deskewed) into the other buffer ----
        if (nb < NBATCHES - 1) {
            float* dst = &s_win[buf ^ 1][warp][0];
            int k0 = 4 * lane - dn;
            if (k0 >= 0) dst[k0] = x0.x;
            if (k0 + 1 >= 0) dst[k0 + 1] = x0.y;
            if (k0 + 2 >= 0) dst[k0 + 2] = x0.z;
            dst[k0 + 3] = x0.w;
            int k1 = 4 * (lane + 32) - dn;
            dst[k1] = x1.x; dst[k1 + 1] = x1.y; dst[k1 + 2] = x1.z; dst[k1 + 3] = x1.w;
            if (lane == 0) {
                int k2 = 256 - dn;
                dst[k2] = x2.x; dst[k2 + 1] = x2.y; dst[k2 + 2] = x2.z; dst[k2 + 3] = x2.w;
            }
        }
        __syncthreads();
    }

    // ---- store per-group partials ----
    {
        float4* p1 = (float4*)&s_s1[g * Ln + 4 * t];
        float4* p2 = (float4*)&s_s2[g * Ln + 4 * t];
        *p1 = make_float4(a0, a1, a2, a3);
        *p2 = make_float4(q0, q1, q2, q3);
    }
    __syncthreads();

    // combine across the 4 r-groups: thread tid owns l = tid
    float S1 = s_s1[tid] + s_s1[Ln + tid] + s_s1[2 * Ln + tid] + s_s1[3 * Ln + tid];
    float S2 = s_s2[tid] + s_s2[Ln + tid] + s_s2[2 * Ln + tid] + s_s2[3 * Ln + tid];

    // Hann half-window at l = tid
    float wl = 0.5f - 0.5f * cosf(3.14159265358979323846f * (float)tid * (1.0f / 255.0f));
    float sw1 = wl * S1;
    float sw2 = (wl * wl) * S2;

    float num_p = sw2;
    float den_p = (sw2 - sw1 * sw1 * (1.0f / (float)Rn)) * (1.0f / (float)(Rn - 1));

    const unsigned FULL = 0xFFFFFFFFu;
#pragma unroll
    for (int off = 16; off > 0; off >>= 1) {
        num_p += __shfl_down_sync(FULL, num_p, off);
        den_p += __shfl_down_sync(FULL, den_p, off);
    }
    if (lane == 0) {
        s_red[warp * 2 + 0] = num_p;
        s_red[warp * 2 + 1] = den_p;
    }
    __syncthreads();
    if (warp == 0) {
        float n  = (lane < 8) ? s_red[lane * 2 + 0] : 0.0f;
        float dd = (lane < 8) ? s_red[lane * 2 + 1] : 0.0f;
#pragma unroll
        for (int off = 4; off > 0; off >>= 1) {
            n  += __shfl_down_sync(FULL, n, off);
            dd += __shfl_down_sync(FULL, dd, off);
        }
        if (lane == 0) {
            float num = n * (1.0f / ((float)Rn * (float)Ln));
            float den = dd * (1.0f / (float)Ln) + 0.001f;
            out[(size_t)b1 * B2n + b2] = num / den;
        }
    }
}

extern "C" void kernel_launch(void* const* d_in, const int* in_sizes, int n_in,
                              void* d_out, int out_size)
{
    const float* recordings         = (const float*)d_in[0];
    const float* sample_locations   = (const float*)d_in[1];
    const float* emitter_location   = (const float*)d_in[2];
    const float* receiver_locations = (const float*)d_in[3];
    float* out = (float*)d_out;

    dim3 grid(B2n, B1n);
    dim3 block(Ln);
    tof_predictor_kernel<<<grid, block>>>(recordings, sample_locations,
                                          emitter_location, receiver_locations, out);
}

// round 9
// speedup vs baseline: 2.0144x; 2.0144x over previous
#include <cuda_runtime.h>
#include <math.h>

#define B1n 4
#define B2n 1024
#define Rn  64
#define Tn  8192
#define Ln  256

// 256 threads = 64 l-threads x 4 r-groups (16 receivers each).
// Thread handles l = 4t..4t+3 via two aligned LDG.128 (lane-contiguous).
// r-loop processed in chunks of 4 receivers: all 8 LDG.128 issued back-to-back
// (MLP=8/warp) before any select/math, to hide L1 queue latency.
// Misalignment d = i0 & 3 resolved branch-free (11 FSEL, warp-uniform).

__global__ void __launch_bounds__(Ln)
tof_predictor_kernel(const float* __restrict__ rec,        // (B1,R,T)
                     const float* __restrict__ samp,       // (B1,B2,3)
                     const float* __restrict__ emit,       // (3,)
                     const float* __restrict__ recv,       // (R,3)
                     float* __restrict__ out)              // (B1,B2)
{
    const int b2  = blockIdx.x;
    const int b1  = blockIdx.y;
    const int tid = threadIdx.x;

    __shared__ float2 s_pr[Rn];          // {frac, as_float(((r*Tn+i0a)<<2)|d)}
    __shared__ float  s_s1[4 * Ln];
    __shared__ float  s_s2[4 * Ln];
    __shared__ float  s_red[16];

    // ---- precompute per-receiver aligned base + d + frac (threads 0..63) ----
    const float fs_c = 96000.0f / 343.0f;
    if (tid < Rn) {
        const float* sp = samp + ((size_t)b1 * B2n + b2) * 3;
        float sx = sp[0], sy = sp[1], sz = sp[2];
        float ex = sx - emit[0], ey = sy - emit[1], ez = sz - emit[2];
        float d_e = sqrtf(ex * ex + ey * ey + ez * ez);
        const float* rp = recv + tid * 3;
        float rx = sx - rp[0], ry = sy - rp[1], rz = sz - rp[2];
        float d_r = sqrtf(rx * rx + ry * ry + rz * rz);
        float start = (d_e + d_r) * fs_c;
        int i0 = (int)floorf(start);
        i0 = min(max(i0, 0), Tn - 2 - (Ln - 1) - 3);  // never fires in practice
        float frac = start - (float)i0;
        int i0a = i0 & ~3;
        int d   = i0 & 3;
        int packed = ((tid * Tn + i0a) << 2) | d;
        s_pr[tid] = make_float2(frac, __int_as_float(packed));
    }
    __syncthreads();

    const int g = tid >> 6;        // r-group 0..3 -> r = g*16 .. g*16+15
    const int t = tid & 63;        // l-thread     -> l = 4t .. 4t+3

    const float* recb = rec + (size_t)b1 * Rn * Tn + 4 * t;

    float a0 = 0.f, a1 = 0.f, a2 = 0.f, a3 = 0.f;
    float q0 = 0.f, q1 = 0.f, q2 = 0.f, q3 = 0.f;

    const int r_lo = g * 16;

#pragma unroll
    for (int c = 0; c < 4; ++c) {            // chunks of 4 receivers
        float  fr[4];
        int    dd[4];
        float4 A[4], B[4];

        // ---- load phase: params + 8 global loads, no dependent math ----
#pragma unroll
        for (int k = 0; k < 4; ++k) {
            float2 pr = s_pr[r_lo + 4 * c + k];
            fr[k] = pr.x;
            int o = __float_as_int(pr.y);
            dd[k] = o & 3;
            const float4* p = (const float4*)(recb + (o >> 2));
            A[k] = __ldg(p);
            B[k] = __ldg(p + 1);
        }

        // ---- compute phase ----
#pragma unroll
        for (int k = 0; k < 4; ++k) {
            float f = fr[k];
            bool s2b = (dd[k] & 2) != 0;
            bool s1b = (dd[k] & 1) != 0;

            float v0 = A[k].x, v1 = A[k].y, v2 = A[k].z, v3 = A[k].w;
            float v4 = B[k].x, v5 = B[k].y, v6 = B[k].z, v7 = B[k].w;

            // stage 1: shift by 2 -> u_j = v[j + 2*s2b]
            float u0 = s2b ? v2 : v0;
            float u1 = s2b ? v3 : v1;
            float u2 = s2b ? v4 : v2;
            float u3 = s2b ? v5 : v3;
            float u4 = s2b ? v6 : v4;
            float u5 = s2b ? v7 : v5;
            // stage 2: shift by 1 -> w_j = u[j + s1b]
            float w0 = s1b ? u1 : u0;
            float w1 = s1b ? u2 : u1;
            float w2 = s1b ? u3 : u2;
            float w3 = s1b ? u4 : u3;
            float w4 = s1b ? u5 : u4;

            float e0 = fmaf(f, w1 - w0, w0);
            float e1 = fmaf(f, w2 - w1, w1);
            float e2 = fmaf(f, w3 - w2, w2);
            float e3 = fmaf(f, w4 - w3, w3);

            a0 += e0; q0 = fmaf(e0, e0, q0);
            a1 += e1; q1 = fmaf(e1, e1, q1);
            a2 += e2; q2 = fmaf(e2, e2, q2);
            a3 += e3; q3 = fmaf(e3, e3, q3);
        }
    }

    // store per-group partials
    {
        float4* p1 = (float4*)&s_s1[g * Ln + 4 * t];
        float4* p2 = (float4*)&s_s2[g * Ln + 4 * t];
        *p1 = make_float4(a0, a1, a2, a3);
        *p2 = make_float4(q0, q1, q2, q3);
    }
    __syncthreads();

    // combine across the 4 r-groups: thread tid owns l = tid
    float S1 = s_s1[tid] + s_s1[Ln + tid] + s_s1[2 * Ln + tid] + s_s1[3 * Ln + tid];
    float S2 = s_s2[tid] + s_s2[Ln + tid] + s_s2[2 * Ln + tid] + s_s2[3 * Ln + tid];

    // Hann half-window at l = tid
    float wl = 0.5f - 0.5f * cosf(3.14159265358979323846f * (float)tid * (1.0f / 255.0f));
    float sw1 = wl * S1;
    float sw2 = (wl * wl) * S2;

    float num_p = sw2;
    float den_p = (sw2 - sw1 * sw1 * (1.0f / (float)Rn)) * (1.0f / (float)(Rn - 1));

    const unsigned FULL = 0xFFFFFFFFu;
#pragma unroll
    for (int off = 16; off > 0; off >>= 1) {
        num_p += __shfl_down_sync(FULL, num_p, off);
        den_p += __shfl_down_sync(FULL, den_p, off);
    }
    const int warp = tid >> 5;
    const int lane = tid & 31;
    if (lane == 0) {
        s_red[warp * 2 + 0] = num_p;
        s_red[warp * 2 + 1] = den_p;
    }
    __syncthreads();
    if (warp == 0) {
        float n  = (lane < 8) ? s_red[lane * 2 + 0] : 0.0f;
        float dd2 = (lane < 8) ? s_red[lane * 2 + 1] : 0.0f;
#pragma unroll
        for (int off = 4; off > 0; off >>= 1) {
            n   += __shfl_down_sync(FULL, n, off);
            dd2 += __shfl_down_sync(FULL, dd2, off);
        }
        if (lane == 0) {
            float num = n * (1.0f / ((float)Rn * (float)Ln));
            float den = dd2 * (1.0f / (float)Ln) + 0.001f;
            out[(size_t)b1 * B2n + b2] = num / den;
        }
    }
}

extern "C" void kernel_launch(void* const* d_in, const int* in_sizes, int n_in,
                              void* d_out, int out_size)
{
    const float* recordings         = (const float*)d_in[0];
    const float* sample_locations   = (const float*)d_in[1];
    const float* emitter_location   = (const float*)d_in[2];
    const float* receiver_locations = (const float*)d_in[3];
    float* out = (float*)d_out;

    dim3 grid(B2n, B1n);
    dim3 block(Ln);
    tof_predictor_kernel<<<grid, block>>>(recordings, sample_locations,
                                          emitter_location, receiver_locations, out);
}

// round 10
// speedup vs baseline: 2.0685x; 1.0269x over previous
#include <cuda_runtime.h>
#include <math.h>

#define B1n 4
#define B2n 1024
#define Rn  64
#define Tn  8192
#define Ln  256

// 256 threads = 64 l-threads x 4 r-groups (16 receivers each).
// Receivers within each group are counting-sorted by d = i0 & 3 (deterministic,
// ballot-based). The r-loop runs as four d-specialized sub-loops: the alignment
// select is compile-time -> zero FSEL/ISETP in the hot path. d=0 / d=3 need only
// ONE LDG.128 (+1 shuffle, +1-lane scalar load).

template<int D>
__device__ __forceinline__ void body_d(float2 pr, const float* recb, int lane,
                                       float& a0, float& a1, float& a2, float& a3,
                                       float& q0, float& q1, float& q2, float& q3)
{
    const unsigned FULL = 0xFFFFFFFFu;
    float f = pr.x;
    int   o = __float_as_int(pr.y);
    const float4* p = (const float4*)(recb + o);

    float w0, w1, w2, w3, w4;
    if (D == 0) {
        float4 A = __ldg(p);
        float v4 = __shfl_down_sync(FULL, A.x, 1);
        if (lane == 31) v4 = __ldg((const float*)p + 4);
        w0 = A.x; w1 = A.y; w2 = A.z; w3 = A.w; w4 = v4;
    } else if (D == 1) {
        float4 A = __ldg(p);
        float4 B = __ldg(p + 1);
        w0 = A.y; w1 = A.z; w2 = A.w; w3 = B.x; w4 = B.y;
    } else if (D == 2) {
        float4 A = __ldg(p);
        float4 B = __ldg(p + 1);
        w0 = A.z; w1 = A.w; w2 = B.x; w3 = B.y; w4 = B.z;
    } else {
        float4 B = __ldg(p + 1);
        float vm = __shfl_up_sync(FULL, B.w, 1);
        if (lane == 0) vm = __ldg((const float*)p + 3);
        w0 = vm; w1 = B.x; w2 = B.y; w3 = B.z; w4 = B.w;
    }

    float e0 = fmaf(f, w1 - w0, w0);
    float e1 = fmaf(f, w2 - w1, w1);
    float e2 = fmaf(f, w3 - w2, w2);
    float e3 = fmaf(f, w4 - w3, w3);
    a0 += e0; q0 = fmaf(e0, e0, q0);
    a1 += e1; q1 = fmaf(e1, e1, q1);
    a2 += e2; q2 = fmaf(e2, e2, q2);
    a3 += e3; q3 = fmaf(e3, e3, q3);
}

__global__ void __launch_bounds__(Ln)
tof_predictor_kernel(const float* __restrict__ rec,        // (B1,R,T)
                     const float* __restrict__ samp,       // (B1,B2,3)
                     const float* __restrict__ emit,       // (3,)
                     const float* __restrict__ recv,       // (R,3)
                     float* __restrict__ out)              // (B1,B2)
{
    const int b2  = blockIdx.x;
    const int b1  = blockIdx.y;
    const int tid = threadIdx.x;

    __shared__ float2 s_sorted[Rn];      // per-group, d-sorted {frac, as_float(r*Tn+i0a)}
    __shared__ int    s_cnt[4][4];       // [group][d] counts
    __shared__ int    s_off[4][4];       // [group][d] bucket start
    __shared__ int    s_bnd[4][4];       // [group][j] bucket end
    __shared__ float  s_s1[4 * Ln];
    __shared__ float  s_s2[4 * Ln];
    __shared__ float  s_red[16];

    // ---- precompute + deterministic counting sort by d (threads 0..63) ----
    const float fs_c = 96000.0f / 343.0f;
    float2 packed;
    int my_d = 0, my_rank = 0, my_g = 0;
    if (tid < Rn) {
        const float* sp = samp + ((size_t)b1 * B2n + b2) * 3;
        float sx = sp[0], sy = sp[1], sz = sp[2];
        float ex = sx - emit[0], ey = sy - emit[1], ez = sz - emit[2];
        float d_e = sqrtf(ex * ex + ey * ey + ez * ez);
        const float* rp = recv + tid * 3;
        float rx = sx - rp[0], ry = sy - rp[1], rz = sz - rp[2];
        float d_r = sqrtf(rx * rx + ry * ry + rz * rz);
        float start = (d_e + d_r) * fs_c;
        int i0 = (int)floorf(start);
        i0 = min(max(i0, 0), Tn - 2 - (Ln - 1) - 7);  // never fires in practice
        float frac = start - (float)i0;
        int i0a = i0 & ~3;
        my_d = i0 & 3;
        my_g = tid >> 4;                              // receiver tid -> group
        packed = make_float2(frac, __int_as_float(tid * Tn + i0a));

        // deterministic within-bucket rank via match over (group, d)
        unsigned m = __match_any_sync(0xFFFFFFFFu, (my_g << 2) | my_d);
        unsigned lt = m & ((1u << (tid & 31)) - 1u);
        my_rank = __popc(lt);
        if (lt == 0u)                                  // bucket leader in this warp
            s_cnt[my_g][my_d] = __popc(m);
    }
    // zero counts for empty buckets: do it before via init
    // (leaders above may not cover all 16 cells) -> handle by pre-zero:
    __syncthreads();
    // NOTE: s_cnt cells with no leader were never written; zero them safely:
    if (tid < 16) {
        // if no receiver in this (g,d), no leader wrote it. We can't know here
        // without a flag; instead recompute count=0 default was needed BEFORE
        // the match. Use s_off as scratch flag written below instead.
    }
    __syncthreads();
    // The above two syncs establish ordering but s_cnt may hold stale data for
    // empty buckets. Fix: redo with explicit pre-zero pass.
    if (tid < 16) s_off[tid >> 2][tid & 3] = 0;        // s_off as "count2" scratch
    __syncthreads();
    if (tid < Rn) {
        unsigned m = __match_any_sync(0xFFFFFFFFu, (my_g << 2) | my_d);
        unsigned lt = m & ((1u << (tid & 31)) - 1u);
        if (lt == 0u) s_off[my_g][my_d] = __popc(m);
    }
    __syncthreads();
    if (tid < 4) {
        int c0 = s_off[tid][0], c1 = s_off[tid][1], c2 = s_off[tid][2], c3 = s_off[tid][3];
        int o0 = 0, o1 = c0, o2 = c0 + c1, o3 = c0 + c1 + c2;
        s_cnt[tid][0] = o0; s_cnt[tid][1] = o1; s_cnt[tid][2] = o2; s_cnt[tid][3] = o3;
        s_bnd[tid][0] = o0 + c0; s_bnd[tid][1] = o1 + c1;
        s_bnd[tid][2] = o2 + c2; s_bnd[tid][3] = o3 + c3;   // == 16
    }
    __syncthreads();
    if (tid < Rn) {
        s_sorted[my_g * 16 + s_cnt[my_g][my_d] + my_rank] = packed;
    }
    __syncthreads();

    const int g = tid >> 6;        // r-group 0..3
    const int t = tid & 63;        // l-thread: l = 4t..4t+3
    const int lane = tid & 31;

    const float* recb = rec + (size_t)b1 * Rn * Tn + 4 * t;

    float a0 = 0.f, a1 = 0.f, a2 = 0.f, a3 = 0.f;
    float q0 = 0.f, q1 = 0.f, q2 = 0.f, q3 = 0.f;

    const int base = g * 16;
    const int e0b = s_bnd[g][0];
    const int e1b = s_bnd[g][1];
    const int e2b = s_bnd[g][2];

    int k = 0;
    for (; k < e0b; ++k)
        body_d<0>(s_sorted[base + k], recb, lane, a0, a1, a2, a3, q0, q1, q2, q3);
    for (; k < e1b; ++k)
        body_d<1>(s_sorted[base + k], recb, lane, a0, a1, a2, a3, q0, q1, q2, q3);
    for (; k < e2b; ++k)
        body_d<2>(s_sorted[base + k], recb, lane, a0, a1, a2, a3, q0, q1, q2, q3);
    for (; k < 16; ++k)
        body_d<3>(s_sorted[base + k], recb, lane, a0, a1, a2, a3, q0, q1, q2, q3);

    // store per-group partials
    {
        float4* p1 = (float4*)&s_s1[g * Ln + 4 * t];
        float4* p2 = (float4*)&s_s2[g * Ln + 4 * t];
        *p1 = make_float4(a0, a1, a2, a3);
        *p2 = make_float4(q0, q1, q2, q3);
    }
    __syncthreads();

    // combine across the 4 r-groups: thread tid owns l = tid
    float S1 = s_s1[tid] + s_s1[Ln + tid] + s_s1[2 * Ln + tid] + s_s1[3 * Ln + tid];
    float S2 = s_s2[tid] + s_s2[Ln + tid] + s_s2[2 * Ln + tid] + s_s2[3 * Ln + tid];

    // Hann half-window at l = tid
    float wl = 0.5f - 0.5f * cosf(3.14159265358979323846f * (float)tid * (1.0f / 255.0f));
    float sw1 = wl * S1;
    float sw2 = (wl * wl) * S2;

    float num_p = sw2;
    float den_p = (sw2 - sw1 * sw1 * (1.0f / (float)Rn)) * (1.0f / (float)(Rn - 1));

    const unsigned FULL = 0xFFFFFFFFu;
#pragma unroll
    for (int off = 16; off > 0; off >>= 1) {
        num_p += __shfl_down_sync(FULL, num_p, off);
        den_p += __shfl_down_sync(FULL, den_p, off);
    }
    const int warp = tid >> 5;
    if (lane == 0) {
        s_red[warp * 2 + 0] = num_p;
        s_red[warp * 2 + 1] = den_p;
    }
    __syncthreads();
    if (warp == 0) {
        float n  = (lane < 8) ? s_red[lane * 2 + 0] : 0.0f;
        float dd = (lane < 8) ? s_red[lane * 2 + 1] : 0.0f;
#pragma unroll
        for (int off = 4; off > 0; off >>= 1) {
            n  += __shfl_down_sync(FULL, n, off);
            dd += __shfl_down_sync(FULL, dd, off);
        }
        if (lane == 0) {
            float num = n * (1.0f / ((float)Rn * (float)Ln));
            float den = dd * (1.0f / (float)Ln) + 0.001f;
            out[(size_t)b1 * B2n + b2] = num / den;
        }
    }
}

extern "C" void kernel_launch(void* const* d_in, const int* in_sizes, int n_in,
                              void* d_out, int out_size)
{
    const float* recordings         = (const float*)d_in[0];
    const float* sample_locations   = (const float*)d_in[1];
    const float* emitter_location   = (const float*)d_in[2];
    const float* receiver_locations = (const float*)d_in[3];
    float* out = (float*)d_out;

    dim3 grid(B2n, B1n);
    dim3 block(Ln);
    tof_predictor_kernel<<<grid, block>>>(recordings, sample_locations,
                                          emitter_location, receiver_locations, out);
}